// round 13
// baseline (speedup 1.0000x reference)
#include <cuda_runtime.h>
#include <math.h>

// ---------------- scratch (device globals; no allocation allowed) ----------
__device__ float g_scores[512];         // attn logits
__device__ float g_ctx_part[8 * 2048];  // split-K context partials
__device__ float g_ctx[2048];           // reduced context
__device__ float g_x[2048];             // relu(attn_combine)
__device__ float g_gates[12288];        // gi[0:6144), gh[6144:12288)
__device__ float g_lmax[512];           // per-block logits max partials
__device__ float g_lsum[512];           // per-block sumexp partials
__device__ int   g_b1, g_b2, g_b3, g_b4; // grid-barrier counters (reset by K3)

#define H 2048
#define V 50257
#define L 512
#define NB 444                          // persistent grid (<= 148*3 and 152*3)

__device__ __forceinline__ float warpSum(float v) {
#pragma unroll
    for (int o = 16; o; o >>= 1) v += __shfl_down_sync(0xffffffffu, v, o);
    return v;
}

// Software grid barrier: all `target` blocks must be resident (guaranteed:
// grid 444 with launch_bounds(256,3)). Writers' data is fenced before arrive;
// the post-spin __syncthreads orders subsequent reads.
__device__ __forceinline__ void gridBar(int* cnt, int target) {
    __syncthreads();
    if (threadIdx.x == 0) {
        __threadfence();
        atomicAdd(cnt, 1);
        while (*(volatile int*)cnt < target) __nanosleep(64);
    }
    __syncthreads();
}

// ---- 8-float4 chunk helpers (A/B pipelined dot; best for logits) ----
__device__ __forceinline__ void loadChunk(float4* dst, const float4* __restrict__ w4,
                                          int lane) {
#pragma unroll
    for (int j = 0; j < 8; j++) dst[j] = __ldcs(&w4[lane + 32 * j]);
}
__device__ __forceinline__ float dotChunk(const float4* wr, const float4* __restrict__ sv,
                                          int lane) {
    float a0 = 0.f, a1 = 0.f, a2 = 0.f, a3 = 0.f;
#pragma unroll
    for (int j = 0; j < 8; j++) {
        float4 v = sv[lane + 32 * j];
        a0 += wr[j].x * v.x;
        a1 += wr[j].y * v.y;
        a2 += wr[j].z * v.z;
        a3 += wr[j].w * v.w;
    }
    return (a0 + a1) + (a2 + a3);
}
template <int NC>
__device__ __forceinline__ float warpRowDot(const float4* __restrict__ w4,
                                            const float4* __restrict__ sv,
                                            int lane) {
    float4 A[8], B[8];
    loadChunk(A, w4, lane);
    float acc = 0.f;
#pragma unroll
    for (int c = 0; c < NC; c++) {
        float4* cur = (c & 1) ? B : A;
        float4* nxt = (c & 1) ? A : B;
        if (c + 1 < NC) loadChunk(nxt, w4 + (c + 1) * 256, lane);
        acc += dotChunk(cur, sv + c * 256, lane);
    }
    return warpSum(acc);
}

// ---- 16-float4 front-batched dot (measured best for H-length gate rows) ----
__device__ __forceinline__ float warpDot512(const float4* __restrict__ w4,
                                            const float4* __restrict__ sv,
                                            int lane) {
    float4 wr[16];
#pragma unroll
    for (int j = 0; j < 16; j++) wr[j] = __ldcs(&w4[lane + 32 * j]);
    float a0 = 0.f, a1 = 0.f, a2 = 0.f, a3 = 0.f;
#pragma unroll
    for (int j = 0; j < 16; j++) {
        float4 v = sv[lane + 32 * j];
        a0 += wr[j].x * v.x;
        a1 += wr[j].y * v.y;
        a2 += wr[j].z * v.z;
        a3 += wr[j].w * v.w;
    }
    return warpSum((a0 + a1) + (a2 + a3));
}

// ---------------------------------------------------------------------------
// K1: fused front — attn + softmax + context + combine + GRU gates.
// Blocks [0,64): attention chain. Blocks [64,444): w_hh stream (concurrent).
// Then all 444: combine, then ih. Grid barriers between phases.
__global__ void __launch_bounds__(256, 3)
k_front(const int* __restrict__ token, const float* __restrict__ hidden,
        const float* __restrict__ embedding, const float* __restrict__ enc,
        const float* __restrict__ attn_W, const float* __restrict__ attn_b,
        const float* __restrict__ comb_W, const float* __restrict__ comb_b,
        const float* __restrict__ w_ih, const float* __restrict__ w_hh,
        const float* __restrict__ b_ih, const float* __restrict__ b_hh,
        float* __restrict__ out_aw) {
    __shared__ float4 sv[1024];     // 16 KB staging
    __shared__ float s_e[L];
    __shared__ float sred[16];
    int tid = threadIdx.x, lane = tid & 31, warp = tid >> 5;
    int bid = blockIdx.x;
    const float4* emb4 = (const float4*)(embedding + (size_t)__ldg(token) * H);
    const float4* hid4 = (const float4*)hidden;

    if (bid < 64) {
        // ---- phase A: attention scores (8 rows per block) ----
#pragma unroll
        for (int k = 0; k < 2; k++) {
            int i = tid + 256 * k;
            sv[i] = __ldg(&emb4[i]);
            sv[i + 512] = __ldg(&hid4[i]);
        }
        __syncthreads();
        {
            int row = bid * 8 + warp;
            const float4* w4 = (const float4*)(attn_W + (size_t)row * 2 * H);
            float a = warpRowDot<4>(w4, sv, lane);
            if (lane == 0) g_scores[row] = a + __ldg(&attn_b[row]);
        }
        gridBar(&g_b1, 64);
        // ---- phase B: local softmax + context partial ----
        {
            float v0 = g_scores[tid], v1 = g_scores[tid + 256];
            float m = fmaxf(v0, v1);
#pragma unroll
            for (int o = 16; o; o >>= 1) m = fmaxf(m, __shfl_down_sync(0xffffffffu, m, o));
            if (lane == 0) sred[warp] = m;
            __syncthreads();
            if (warp == 0) {
                m = (lane < 8) ? sred[lane] : -1e30f;
#pragma unroll
                for (int o = 4; o; o >>= 1) m = fmaxf(m, __shfl_down_sync(0xffffffffu, m, o));
                if (lane == 0) sred[8] = m;
            }
            __syncthreads();
            m = sred[8];
            float e0 = expf(v0 - m), e1 = expf(v1 - m);
            s_e[tid] = e0;
            s_e[tid + 256] = e1;
            float sum = warpSum(e0 + e1);
            if (lane == 0) sred[warp] = sum;
            __syncthreads();
            if (warp == 0) {
                sum = (lane < 8) ? sred[lane] : 0.f;
                sum = warpSum(sum);
                if (lane == 0) sred[9] = sum;
            }
            __syncthreads();
            float inv = 1.f / sred[9];
            if (bid == 0) {
                out_aw[tid] = s_e[tid] * inv;
                out_aw[tid + 256] = s_e[tid + 256] * inv;
            }
            int bx = bid & 7, by = bid >> 3;
            int r0 = by * 64;
            int col = bx * 256 + tid;
            float a0 = 0.f, a1 = 0.f, a2 = 0.f, a3 = 0.f;
#pragma unroll 4
            for (int l = 0; l < 64; l += 4) {
                a0 += s_e[r0 + l + 0] * __ldcs(&enc[(size_t)(r0 + l + 0) * H + col]);
                a1 += s_e[r0 + l + 1] * __ldcs(&enc[(size_t)(r0 + l + 1) * H + col]);
                a2 += s_e[r0 + l + 2] * __ldcs(&enc[(size_t)(r0 + l + 2) * H + col]);
                a3 += s_e[r0 + l + 3] * __ldcs(&enc[(size_t)(r0 + l + 3) * H + col]);
            }
            g_ctx_part[by * H + col] = ((a0 + a1) + (a2 + a3)) * inv;
        }
        gridBar(&g_b2, 64);
        // ---- phase C: reduce this block's 32-col slice into g_ctx ----
        if (tid < 32) {
            int col = bid * 32 + tid;
            float c = g_ctx_part[col];
#pragma unroll
            for (int p = 1; p < 8; p++) c += g_ctx_part[p * H + col];
            g_ctx[col] = c;
        }
    } else {
        // ---- concurrent w_hh stream (blocks 64..443, 3040 warps) ----
#pragma unroll
        for (int k = 0; k < 2; k++) sv[tid + 256 * k] = __ldg(&hid4[tid + 256 * k]);
        __syncthreads();
        for (int r = (bid - 64) * 8 + warp; r < 3 * H; r += 3040) {
            const float4* w4 = (const float4*)(w_hh + (size_t)r * H);
            float a = warpDot512(w4, sv, lane);
            if (lane == 0) g_gates[3 * H + r] = a + __ldg(&b_hh[r]);
        }
    }

    gridBar(&g_b3, NB);
    // ---- phase D: combine (all blocks stage [emb|ctx]; rows 0..2047) ----
    {
        const float4* ctx4 = (const float4*)g_ctx;
#pragma unroll
        for (int k = 0; k < 2; k++) {
            int i = tid + 256 * k;
            sv[i] = __ldg(&emb4[i]);
            sv[i + 512] = ctx4[i];
        }
        __syncthreads();
        int gw = bid * 8 + warp;
        if (gw < H) {
            const float4* w4 = (const float4*)(comb_W + (size_t)gw * 2 * H);
            float a = warpRowDot<4>(w4, sv, lane);
            if (lane == 0) g_x[gw] = fmaxf(a + __ldg(&comb_b[gw]), 0.f);
        }
    }
    gridBar(&g_b4, NB);
    // ---- phase E: w_ih rows (all 3552 warps, rows 0..6143) ----
    {
        const float4* x4 = (const float4*)g_x;
#pragma unroll
        for (int k = 0; k < 2; k++) sv[tid + 256 * k] = x4[tid + 256 * k];
        __syncthreads();
        for (int r = bid * 8 + warp; r < 3 * H; r += NB * 8) {
            const float4* w4 = (const float4*)(w_ih + (size_t)r * H);
            float a = warpDot512(w4, sv, lane);
            if (lane == 0) g_gates[r] = a + __ldg(&b_ih[r]);
        }
    }
}

// ---------------------------------------------------------------------------
// K2: logits GEMV (412 MB). Persistent 444 blocks; h_new computed in every
// block's prologue from g_gates (L2-resident, deterministic); block 0 writes
// out_h. Chunked A/B pipeline + cross-row prefetch (clamped to row 0).
__global__ void __launch_bounds__(256, 3)
k_logits(const float* __restrict__ out_W, const float* __restrict__ out_b,
         const float* __restrict__ hidden, float* __restrict__ out,
         float* __restrict__ out_h) {
    __shared__ float4 sv[512];
    __shared__ float smm[8], sss[8];
    int tid = threadIdx.x, lane = tid & 31, warp = tid >> 5;
    float* svf = (float*)sv;
    const float* gi = g_gates;
    const float* gh = g_gates + 3 * H;
#pragma unroll
    for (int k = 0; k < 8; k++) {
        int i = tid + 256 * k;   // 0..2047
        float r = 1.f / (1.f + expf(-(gi[i] + gh[i])));
        float z = 1.f / (1.f + expf(-(gi[H + i] + gh[H + i])));
        float n = tanhf(gi[2 * H + i] + r * gh[2 * H + i]);
        float hn = (1.f - z) * n + z * hidden[i];
        svf[i] = hn;
        if (blockIdx.x == 0) out_h[i] = hn;
    }
    __syncthreads();
    const int stride = NB * 8;  // 3552
    int row = blockIdx.x * 8 + warp;
    float pm = -1e30f, ps = 0.f;
    if (row < V) {
        float4 A[8], B[8];
        const float4* wp = (const float4*)(out_W + (size_t)row * H);
        loadChunk(A, wp, lane);
        while (true) {
            int nrow = row + stride;
            const float4* wpn = (nrow < V) ? (const float4*)(out_W + (size_t)nrow * H)
                                           : (const float4*)out_W;
            loadChunk(B, wp + 256, lane);
            float acc = dotChunk(A, sv, lane);
            loadChunk(A, wpn, lane);
            acc += dotChunk(B, sv + 256, lane);
            float a = warpSum(acc);
            if (lane == 0) {
                float val = a + __ldg(&out_b[row]);
                out[row] = val;
                float M = fmaxf(pm, val);
                ps = ps * expf(pm - M) + expf(val - M);
                pm = M;
            }
            if (nrow >= V) break;
            row = nrow;
            wp = wpn;
        }
    }
    if (lane == 0) { smm[warp] = pm; sss[warp] = ps; }
    __syncthreads();
    if (tid == 0) {
        float m = smm[0], s = sss[0];
#pragma unroll
        for (int k = 1; k < 8; k++) {
            float M = fmaxf(m, smm[k]);
            s = s * expf(m - M) + sss[k] * expf(smm[k] - M);
            m = M;
        }
        g_lmax[blockIdx.x] = m;
        g_lsum[blockIdx.x] = s;
    }
}

// ---------------------------------------------------------------------------
// K3: merge 444 (max,sum) partials per block (fixed order), subtract lse,
// and reset K1's barrier counters for the next graph replay.
__global__ void k_logsoftmax(float* __restrict__ out) {
    __shared__ float smm[8], sss[8];
    __shared__ float s_lse;
    int tid = threadIdx.x, lane = tid & 31, warp = tid >> 5;
    if (blockIdx.x == 0 && tid == 0) { g_b1 = 0; g_b2 = 0; g_b3 = 0; g_b4 = 0; }
    float m = -1e30f, s = 0.f;
    for (int i = tid; i < NB; i += 256) {
        float m2 = g_lmax[i], s2 = g_lsum[i];
        float M = fmaxf(m, m2);
        s = s * expf(m - M) + s2 * expf(m2 - M);
        m = M;
    }
#pragma unroll
    for (int o = 16; o; o >>= 1) {
        float m2 = __shfl_down_sync(0xffffffffu, m, o);
        float s2 = __shfl_down_sync(0xffffffffu, s, o);
        float M = fmaxf(m, m2);
        s = s * expf(m - M) + s2 * expf(m2 - M);
        m = M;
    }
    if (lane == 0) { smm[warp] = m; sss[warp] = s; }
    __syncthreads();
    if (tid == 0) {
        m = smm[0]; s = sss[0];
#pragma unroll
        for (int k = 1; k < 8; k++) {
            float M = fmaxf(m, smm[k]);
            s = s * expf(m - M) + sss[k] * expf(smm[k] - M);
            m = M;
        }
        s_lse = m + logf(s);
    }
    __syncthreads();
    int i = blockIdx.x * 256 + tid;
    if (i < V) out[i] -= s_lse;
}

extern "C" void kernel_launch(void* const* d_in, const int* in_sizes, int n_in,
                              void* d_out, int out_size) {
    const int*   token     = (const int*)d_in[0];
    const float* hidden    = (const float*)d_in[1];
    const float* enc       = (const float*)d_in[2];
    const float* embedding = (const float*)d_in[3];
    const float* attn_W    = (const float*)d_in[4];
    const float* attn_b    = (const float*)d_in[5];
    const float* comb_W    = (const float*)d_in[6];
    const float* comb_b    = (const float*)d_in[7];
    const float* w_ih      = (const float*)d_in[8];
    const float* w_hh      = (const float*)d_in[9];
    const float* b_ih      = (const float*)d_in[10];
    const float* b_hh      = (const float*)d_in[11];
    const float* out_W     = (const float*)d_in[12];
    const float* out_b     = (const float*)d_in[13];

    float* out = (float*)d_out;
    float* out_logits = out;
    float* out_h      = out + V;
    float* out_aw     = out + V + H;

    k_front<<<NB, 256>>>(token, hidden, embedding, enc, attn_W, attn_b,
                         comb_W, comb_b, w_ih, w_hh, b_ih, b_hh, out_aw);
    k_logits<<<NB, 256>>>(out_W, out_b, hidden, out_logits, out_h);
    k_logsoftmax<<<(V + 255) / 256, 256>>>(out_logits);
}

// round 14
// speedup vs baseline: 1.0048x; 1.0048x over previous
#include <cuda_runtime.h>
#include <math.h>

// ---------------- scratch (device globals; no allocation allowed) ----------
__device__ float g_scores[512];         // attn logits
__device__ float g_ctx_part[8 * 2048];  // split-K context partials
__device__ float g_ctx[2048];           // reduced context
__device__ float g_comb_emb[2048];      // comb_W[:, :H] @ emb partial
__device__ float g_x[2048];             // relu(attn_combine)
__device__ float g_gates[12288];        // gi[0:6144), gh[6144:12288)
__device__ float g_lmax[512];           // per-block logits max partials
__device__ float g_lsum[512];           // per-block sumexp partials
__device__ int   g_b1, g_b2, g_b3, g_b4; // grid-barrier counters (reset by K3)

#define H 2048
#define V 50257
#define L 512
#define NB 444                          // persistent grid (<= 148*3 and 152*3)

__device__ __forceinline__ float warpSum(float v) {
#pragma unroll
    for (int o = 16; o; o >>= 1) v += __shfl_down_sync(0xffffffffu, v, o);
    return v;
}

// Software grid barrier: all `target` blocks resident (grid 444, occ 3).
__device__ __forceinline__ void gridBar(int* cnt, int target) {
    __syncthreads();
    if (threadIdx.x == 0) {
        __threadfence();
        atomicAdd(cnt, 1);
        while (*(volatile int*)cnt < target) __nanosleep(64);
    }
    __syncthreads();
}

// ---- 8-float4 chunk helpers (A/B pipelined dot; best for 2H rows/logits) ----
__device__ __forceinline__ void loadChunk(float4* dst, const float4* __restrict__ w4,
                                          int lane) {
#pragma unroll
    for (int j = 0; j < 8; j++) dst[j] = __ldcs(&w4[lane + 32 * j]);
}
__device__ __forceinline__ float dotChunk(const float4* wr, const float4* __restrict__ sv,
                                          int lane) {
    float a0 = 0.f, a1 = 0.f, a2 = 0.f, a3 = 0.f;
#pragma unroll
    for (int j = 0; j < 8; j++) {
        float4 v = sv[lane + 32 * j];
        a0 += wr[j].x * v.x;
        a1 += wr[j].y * v.y;
        a2 += wr[j].z * v.z;
        a3 += wr[j].w * v.w;
    }
    return (a0 + a1) + (a2 + a3);
}
template <int NC>
__device__ __forceinline__ float warpRowDot(const float4* __restrict__ w4,
                                            const float4* __restrict__ sv,
                                            int lane) {
    float4 A[8], B[8];
    loadChunk(A, w4, lane);
    float acc = 0.f;
#pragma unroll
    for (int c = 0; c < NC; c++) {
        float4* cur = (c & 1) ? B : A;
        float4* nxt = (c & 1) ? A : B;
        if (c + 1 < NC) loadChunk(nxt, w4 + (c + 1) * 256, lane);
        acc += dotChunk(cur, sv + c * 256, lane);
    }
    return warpSum(acc);
}

// ---- 16-float4 front-batched dot (measured best for H-length rows) ----
__device__ __forceinline__ float warpDot512(const float4* __restrict__ w4,
                                            const float4* __restrict__ sv,
                                            int lane) {
    float4 wr[16];
#pragma unroll
    for (int j = 0; j < 16; j++) wr[j] = __ldcs(&w4[lane + 32 * j]);
    float a0 = 0.f, a1 = 0.f, a2 = 0.f, a3 = 0.f;
#pragma unroll
    for (int j = 0; j < 16; j++) {
        float4 v = sv[lane + 32 * j];
        a0 += wr[j].x * v.x;
        a1 += wr[j].y * v.y;
        a2 += wr[j].z * v.z;
        a3 += wr[j].w * v.w;
    }
    return warpSum((a0 + a1) + (a2 + a3));
}

// ---------------------------------------------------------------------------
// K1: fused front.
// Phase 0: blocks [0,64) attention chain; blocks [64,444) stream w_hh (6144
//   rows) + comb_W emb-half (2048 rows) = 8192 tasks over 3040 warps.
// Phase D': all blocks, comb_W ctx-half (2048 one-shot warp tasks) -> x.
// Phase E: all blocks, w_ih (6144 rows).
__global__ void __launch_bounds__(256, 3)
k_front(const int* __restrict__ token, const float* __restrict__ hidden,
        const float* __restrict__ embedding, const float* __restrict__ enc,
        const float* __restrict__ attn_W, const float* __restrict__ attn_b,
        const float* __restrict__ comb_W, const float* __restrict__ comb_b,
        const float* __restrict__ w_ih, const float* __restrict__ w_hh,
        const float* __restrict__ b_ih, const float* __restrict__ b_hh,
        float* __restrict__ out_aw) {
    __shared__ float4 sv[1024];     // 16 KB staging
    __shared__ float s_e[L];
    __shared__ float sred[16];
    int tid = threadIdx.x, lane = tid & 31, warp = tid >> 5;
    int bid = blockIdx.x;
    const float4* emb4 = (const float4*)(embedding + (size_t)__ldg(token) * H);
    const float4* hid4 = (const float4*)hidden;

    // stage [emb | hidden] once (both phase-0 roles need this layout)
#pragma unroll
    for (int k = 0; k < 2; k++) {
        int i = tid + 256 * k;
        sv[i] = __ldg(&emb4[i]);
        sv[i + 512] = __ldg(&hid4[i]);
    }
    __syncthreads();

    if (bid < 64) {
        // ---- attention scores (8 rows per block, input = cat(emb,h)) ----
        {
            int row = bid * 8 + warp;
            const float4* w4 = (const float4*)(attn_W + (size_t)row * 2 * H);
            float a = warpRowDot<4>(w4, sv, lane);
            if (lane == 0) g_scores[row] = a + __ldg(&attn_b[row]);
        }
        gridBar(&g_b1, 64);
        // ---- local softmax + context partial ----
        {
            float v0 = __ldcg(&g_scores[tid]), v1 = __ldcg(&g_scores[tid + 256]);
            float m = fmaxf(v0, v1);
#pragma unroll
            for (int o = 16; o; o >>= 1) m = fmaxf(m, __shfl_down_sync(0xffffffffu, m, o));
            if (lane == 0) sred[warp] = m;
            __syncthreads();
            if (warp == 0) {
                m = (lane < 8) ? sred[lane] : -1e30f;
#pragma unroll
                for (int o = 4; o; o >>= 1) m = fmaxf(m, __shfl_down_sync(0xffffffffu, m, o));
                if (lane == 0) sred[8] = m;
            }
            __syncthreads();
            m = sred[8];
            float e0 = expf(v0 - m), e1 = expf(v1 - m);
            s_e[tid] = e0;
            s_e[tid + 256] = e1;
            float sum = warpSum(e0 + e1);
            if (lane == 0) sred[warp] = sum;
            __syncthreads();
            if (warp == 0) {
                sum = (lane < 8) ? sred[lane] : 0.f;
                sum = warpSum(sum);
                if (lane == 0) sred[9] = sum;
            }
            __syncthreads();
            float inv = 1.f / sred[9];
            if (bid == 0) {
                out_aw[tid] = s_e[tid] * inv;
                out_aw[tid + 256] = s_e[tid + 256] * inv;
            }
            int bx = bid & 7, by = bid >> 3;
            int r0 = by * 64;
            int col = bx * 256 + tid;
            float a0 = 0.f, a1 = 0.f, a2 = 0.f, a3 = 0.f;
#pragma unroll 4
            for (int l = 0; l < 64; l += 4) {
                a0 += s_e[r0 + l + 0] * __ldcs(&enc[(size_t)(r0 + l + 0) * H + col]);
                a1 += s_e[r0 + l + 1] * __ldcs(&enc[(size_t)(r0 + l + 1) * H + col]);
                a2 += s_e[r0 + l + 2] * __ldcs(&enc[(size_t)(r0 + l + 2) * H + col]);
                a3 += s_e[r0 + l + 3] * __ldcs(&enc[(size_t)(r0 + l + 3) * H + col]);
            }
            g_ctx_part[by * H + col] = ((a0 + a1) + (a2 + a3)) * inv;
        }
        gridBar(&g_b2, 64);
        // ---- reduce this block's 32-col slice into g_ctx ----
        if (tid < 32) {
            int col = bid * 32 + tid;
            float c = __ldcg(&g_ctx_part[col]);
#pragma unroll
            for (int p = 1; p < 8; p++) c += __ldcg(&g_ctx_part[p * H + col]);
            g_ctx[col] = c;
        }
    } else {
        // ---- concurrent stream: w_hh rows (t<6144) + comb emb-half rows ----
        for (int t = (bid - 64) * 8 + warp; t < 8192; t += 3040) {
            if (t < 6144) {
                const float4* w4 = (const float4*)(w_hh + (size_t)t * H);
                float a = warpDot512(w4, sv + 512, lane);
                if (lane == 0) g_gates[3 * H + t] = a + __ldg(&b_hh[t]);
            } else {
                int r = t - 6144;
                const float4* w4 = (const float4*)(comb_W + (size_t)r * 2 * H);
                float a = warpDot512(w4, sv, lane);
                if (lane == 0) g_comb_emb[r] = a;
            }
        }
    }

    gridBar(&g_b3, NB);
    // ---- phase D': comb_W ctx-half -> x (2048 one-shot warp tasks) ----
    {
        const float4* ctx4 = (const float4*)g_ctx;
#pragma unroll
        for (int k = 0; k < 2; k++) {
            int i = tid + 256 * k;
            sv[i] = __ldcg(&ctx4[i]);
        }
        __syncthreads();
        int gw = bid * 8 + warp;
        if (gw < H) {
            const float4* w4 = (const float4*)(comb_W + (size_t)gw * 2 * H) + 512;
            float a = warpDot512(w4, sv, lane);
            if (lane == 0)
                g_x[gw] = fmaxf(a + __ldcg(&g_comb_emb[gw]) + __ldg(&comb_b[gw]), 0.f);
        }
    }
    gridBar(&g_b4, NB);
    // ---- phase E: w_ih rows (6144 rows over 3552 warps) ----
    {
        const float4* x4 = (const float4*)g_x;
#pragma unroll
        for (int k = 0; k < 2; k++) sv[tid + 256 * k] = __ldcg(&x4[tid + 256 * k]);
        __syncthreads();
        for (int r = bid * 8 + warp; r < 3 * H; r += NB * 8) {
            const float4* w4 = (const float4*)(w_ih + (size_t)r * H);
            float a = warpDot512(w4, sv, lane);
            if (lane == 0) g_gates[r] = a + __ldg(&b_ih[r]);
        }
    }
}

// ---------------------------------------------------------------------------
// K2: logits GEMV (412 MB). Persistent 444 blocks; h_new in every block's
// prologue (deterministic, L2-resident); block 0 writes out_h. Chunked A/B
// pipeline + cross-row prefetch (clamped to row 0).
__global__ void __launch_bounds__(256, 3)
k_logits(const float* __restrict__ out_W, const float* __restrict__ out_b,
         const float* __restrict__ hidden, float* __restrict__ out,
         float* __restrict__ out_h) {
    __shared__ float4 sv[512];
    __shared__ float smm[8], sss[8];
    int tid = threadIdx.x, lane = tid & 31, warp = tid >> 5;
    float* svf = (float*)sv;
    const float* gi = g_gates;
    const float* gh = g_gates + 3 * H;
#pragma unroll
    for (int k = 0; k < 8; k++) {
        int i = tid + 256 * k;   // 0..2047
        float r = 1.f / (1.f + expf(-(gi[i] + gh[i])));
        float z = 1.f / (1.f + expf(-(gi[H + i] + gh[H + i])));
        float n = tanhf(gi[2 * H + i] + r * gh[2 * H + i]);
        float hn = (1.f - z) * n + z * hidden[i];
        svf[i] = hn;
        if (blockIdx.x == 0) out_h[i] = hn;
    }
    __syncthreads();
    const int stride = NB * 8;  // 3552
    int row = blockIdx.x * 8 + warp;
    float pm = -1e30f, ps = 0.f;
    if (row < V) {
        float4 A[8], B[8];
        const float4* wp = (const float4*)(out_W + (size_t)row * H);
        loadChunk(A, wp, lane);
        while (true) {
            int nrow = row + stride;
            const float4* wpn = (nrow < V) ? (const float4*)(out_W + (size_t)nrow * H)
                                           : (const float4*)out_W;
            loadChunk(B, wp + 256, lane);
            float acc = dotChunk(A, sv, lane);
            loadChunk(A, wpn, lane);
            acc += dotChunk(B, sv + 256, lane);
            float a = warpSum(acc);
            if (lane == 0) {
                float val = a + __ldg(&out_b[row]);
                out[row] = val;
                float M = fmaxf(pm, val);
                ps = ps * expf(pm - M) + expf(val - M);
                pm = M;
            }
            if (nrow >= V) break;
            row = nrow;
            wp = wpn;
        }
    }
    if (lane == 0) { smm[warp] = pm; sss[warp] = ps; }
    __syncthreads();
    if (tid == 0) {
        float m = smm[0], s = sss[0];
#pragma unroll
        for (int k = 1; k < 8; k++) {
            float M = fmaxf(m, smm[k]);
            s = s * expf(m - M) + sss[k] * expf(smm[k] - M);
            m = M;
        }
        g_lmax[blockIdx.x] = m;
        g_lsum[blockIdx.x] = s;
    }
}

// ---------------------------------------------------------------------------
// K3: merge 444 (max,sum) partials per block (fixed order), subtract lse,
// and reset K1's barrier counters for the next graph replay.
__global__ void k_logsoftmax(float* __restrict__ out) {
    __shared__ float smm[8], sss[8];
    __shared__ float s_lse;
    int tid = threadIdx.x, lane = tid & 31, warp = tid >> 5;
    if (blockIdx.x == 0 && tid == 0) { g_b1 = 0; g_b2 = 0; g_b3 = 0; g_b4 = 0; }
    float m = -1e30f, s = 0.f;
    for (int i = tid; i < NB; i += 256) {
        float m2 = g_lmax[i], s2 = g_lsum[i];
        float M = fmaxf(m, m2);
        s = s * expf(m - M) + s2 * expf(m2 - M);
        m = M;
    }
#pragma unroll
    for (int o = 16; o; o >>= 1) {
        float m2 = __shfl_down_sync(0xffffffffu, m, o);
        float s2 = __shfl_down_sync(0xffffffffu, s, o);
        float M = fmaxf(m, m2);
        s = s * expf(m - M) + s2 * expf(m2 - M);
        m = M;
    }
    if (lane == 0) { smm[warp] = m; sss[warp] = s; }
    __syncthreads();
    if (tid == 0) {
        m = smm[0]; s = sss[0];
#pragma unroll
        for (int k = 1; k < 8; k++) {
            float M = fmaxf(m, smm[k]);
            s = s * expf(m - M) + sss[k] * expf(smm[k] - M);
            m = M;
        }
        s_lse = m + logf(s);
    }
    __syncthreads();
    int i = blockIdx.x * 256 + tid;
    if (i < V) out[i] -= s_lse;
}

extern "C" void kernel_launch(void* const* d_in, const int* in_sizes, int n_in,
                              void* d_out, int out_size) {
    const int*   token     = (const int*)d_in[0];
    const float* hidden    = (const float*)d_in[1];
    const float* enc       = (const float*)d_in[2];
    const float* embedding = (const float*)d_in[3];
    const float* attn_W    = (const float*)d_in[4];
    const float* attn_b    = (const float*)d_in[5];
    const float* comb_W    = (const float*)d_in[6];
    const float* comb_b    = (const float*)d_in[7];
    const float* w_ih      = (const float*)d_in[8];
    const float* w_hh      = (const float*)d_in[9];
    const float* b_ih      = (const float*)d_in[10];
    const float* b_hh      = (const float*)d_in[11];
    const float* out_W     = (const float*)d_in[12];
    const float* out_b     = (const float*)d_in[13];

    float* out = (float*)d_out;
    float* out_logits = out;
    float* out_h      = out + V;
    float* out_aw     = out + V + H;

    k_front<<<NB, 256>>>(token, hidden, embedding, enc, attn_W, attn_b,
                         comb_W, comb_b, w_ih, w_hh, b_ih, b_hh, out_aw);
    k_logits<<<NB, 256>>>(out_W, out_b, hidden, out_logits, out_h);
    k_logsoftmax<<<(V + 255) / 256, 256>>>(out_logits);
}